// round 15
// baseline (speedup 1.0000x reference)
#include <cuda_runtime.h>
#include <cuda_bf16.h>
#include <cstdint>

// Problem constants
#define BB 16
#define PP 16
#define CC 1024
#define DD 128

// ---------------------------------------------------------------------------
// Single fused kernel, cluster-scoped softmax (no gpu-scope fences/atomics,
// no second launch):
//   grid = 128 CTAs x 1024 threads, cluster = 8 CTAs.
//   One cluster == one batch b (8 CTAs x 2048 candidates = 16384 = P*C).
//   Each warp owns 64 consecutive candidates (all within one (b,p)).
//   e = exp(dot128(cand_emb, score_w[384:512])) for c < cand_len, else 0.
//   (query/v1/v2 score terms are constant per-b and cancel in the softmax;
//    max-shift unnecessary, |logit| <~ 1.5.)
//   The butterfly reduce leaves the dot in ALL lanes, so lane l keeps
//   candidates 2l, 2l+1 of its warp IN REGISTERS -> outputs written once,
//   already normalized. Denominator exchanged across the cluster via DSMEM.
// ---------------------------------------------------------------------------
__global__ __launch_bounds__(1024, 1) void fused_cluster_kernel(
    const float* __restrict__ cand_emb,   // (B,P,C,D)
    const int*   __restrict__ cand_len,   // (B,P)
    const float* __restrict__ score_w,    // (1, 512)
    float*       __restrict__ out)        // (B, P*C) final softmax
{
    __shared__ float wsum[32];
    __shared__ float cSum;     // this CTA's partial sum (DSMEM-visible)
    __shared__ float sInv;

    const int tid  = threadIdx.x;
    const int lane = tid & 31;
    const int warp = tid >> 5;
    const int bid  = blockIdx.x;              // 0..127

    // CTA covers candidates [bid*2048, +2048) = 2 (b,p) pairs.
    const int bp   = bid * 2 + (warp >> 4);   // warps 0-15 -> bp0, 16-31 -> bp1
    const int clen = __ldg(&cand_len[bp]);

    // candidate-embedding slice of score_w: offset 3*128 = 384
    const float4 wv = reinterpret_cast<const float4*>(score_w + 3 * DD)[lane];

    // this warp's 64 candidates start at flat index n0 = bid*2048 + warp*64
    const float4* __restrict__ src =
        reinterpret_cast<const float4*>(cand_emb) +
        ((size_t)bid * 2048 + (size_t)warp * 64) * 32;   // 32 float4 / cand

    const int cBase = (warp & 15) * 64;       // within-(b,p) candidate base

    float eLo = 0.0f, eHi = 0.0f;             // kept: idx 2*lane, 2*lane+1

    #pragma unroll
    for (int i = 0; i < 16; i++) {
        const int j0 = i * 4;
        const bool v0 = (cBase + j0 + 0) < clen;
        const bool v1 = (cBase + j0 + 1) < clen;
        const bool v2 = (cBase + j0 + 2) < clen;
        const bool v3 = (cBase + j0 + 3) < clen;

        // warp-uniform predicated loads: masked candidates cost no traffic
        float4 a0 = v0 ? src[(size_t)(j0 + 0) * 32 + lane] : make_float4(0.f,0.f,0.f,0.f);
        float4 a1 = v1 ? src[(size_t)(j0 + 1) * 32 + lane] : make_float4(0.f,0.f,0.f,0.f);
        float4 a2 = v2 ? src[(size_t)(j0 + 2) * 32 + lane] : make_float4(0.f,0.f,0.f,0.f);
        float4 a3 = v3 ? src[(size_t)(j0 + 3) * 32 + lane] : make_float4(0.f,0.f,0.f,0.f);

        float s0 = a0.x * wv.x + a0.y * wv.y + a0.z * wv.z + a0.w * wv.w;
        float s1 = a1.x * wv.x + a1.y * wv.y + a1.z * wv.z + a1.w * wv.w;
        float s2 = a2.x * wv.x + a2.y * wv.y + a2.z * wv.z + a2.w * wv.w;
        float s3 = a3.x * wv.x + a3.y * wv.y + a3.z * wv.z + a3.w * wv.w;

        #pragma unroll
        for (int o = 16; o > 0; o >>= 1) {
            s0 += __shfl_xor_sync(0xFFFFFFFFu, s0, o);
            s1 += __shfl_xor_sync(0xFFFFFFFFu, s1, o);
            s2 += __shfl_xor_sync(0xFFFFFFFFu, s2, o);
            s3 += __shfl_xor_sync(0xFFFFFFFFu, s3, o);
        }

        // all lanes hold the sums; compute e (cheap MUFU exp) and keep ours
        const float e0 = v0 ? __expf(s0) : 0.0f;
        const float e1 = v1 ? __expf(s1) : 0.0f;
        const float e2 = v2 ? __expf(s2) : 0.0f;
        const float e3 = v3 ? __expf(s3) : 0.0f;

        // lane l keeps within-warp candidate idx 2l (eLo) and 2l+1 (eHi)
        if (((j0 + 0) >> 1) == lane) eLo = e0;
        if (((j0 + 1) >> 1) == lane) eHi = e1;
        if (((j0 + 2) >> 1) == lane) eLo = e2;
        if (((j0 + 3) >> 1) == lane) eHi = e3;
    }

    // ---- warp sum of its 64 e-values (each lane holds 2) ----
    float wl = eLo + eHi;
    #pragma unroll
    for (int o = 16; o > 0; o >>= 1)
        wl += __shfl_xor_sync(0xFFFFFFFFu, wl, o);
    if (lane == 0) wsum[warp] = wl;
    __syncthreads();

    // ---- block sum -> cSum (cluster-visible smem) ----
    if (warp == 0) {
        float s = wsum[lane];
        #pragma unroll
        for (int o = 16; o > 0; o >>= 1)
            s += __shfl_xor_sync(0xFFFFFFFFu, s, o);
        if (lane == 0) cSum = s;
    }
    // cluster barrier: publishes cSum across the 8 CTAs (release semantics)
    asm volatile("barrier.cluster.arrive.aligned;" ::: "memory");
    asm volatile("barrier.cluster.wait.aligned;"   ::: "memory");

    // ---- warp 0: gather the 8 per-CTA sums via DSMEM, broadcast 1/sum ----
    if (warp == 0) {
        uint32_t localAddr;
        asm("{ .reg .u64 t; cvta.to.shared.u64 t, %1; cvt.u32.u64 %0, t; }"
            : "=r"(localAddr) : "l"(&cSum));
        float ps = 0.0f;
        if (lane < 8) {
            uint32_t remAddr;
            asm("mapa.shared::cluster.u32 %0, %1, %2;"
                : "=r"(remAddr) : "r"(localAddr), "r"(lane));
            asm("ld.shared::cluster.f32 %0, [%1];"
                : "=f"(ps) : "r"(remAddr));
        }
        #pragma unroll
        for (int o = 4; o > 0; o >>= 1)
            ps += __shfl_xor_sync(0xFFFFFFFFu, ps, o);
        if (lane == 0) sInv = 1.0f / ps;
    }
    __syncthreads();
    const float inv = sInv;

    // ---- write this warp's 64 normalized values: one float2 per lane ----
    float2* __restrict__ dst =
        reinterpret_cast<float2*>(out) + (size_t)bid * 1024 + warp * 32 + lane;
    *dst = make_float2(eLo * inv, eHi * inv);

    // keep cluster smem alive until all peers finished their DSMEM reads
    asm volatile("barrier.cluster.arrive.aligned;" ::: "memory");
    asm volatile("barrier.cluster.wait.aligned;"   ::: "memory");
}

// ---------------------------------------------------------------------------
// Inputs (metadata order):
//  0 query  1 path_emb  2 path_len  3 cand_emb  4 cand_len  5..18 weights
// 19 score_w (1,512)   20 score_b
// Output: (B, P*C) float32 = 262144
// ---------------------------------------------------------------------------
extern "C" void kernel_launch(void* const* d_in, const int* in_sizes, int n_in,
                              void* d_out, int out_size) {
    const float* cand_emb = (const float*)d_in[3];
    const int*   cand_len = (const int*)d_in[4];
    const float* score_w  = (const float*)d_in[19];
    float* out = (float*)d_out;

    cudaLaunchConfig_t cfg = {};
    cfg.gridDim  = dim3(128);      // 16 clusters x 8 CTAs = 16 batches
    cfg.blockDim = dim3(1024);
    cfg.dynamicSmemBytes = 0;
    cfg.stream = 0;
    cudaLaunchAttribute attr[1];
    attr[0].id = cudaLaunchAttributeClusterDimension;
    attr[0].val.clusterDim = {8, 1, 1};
    cfg.attrs = attr;
    cfg.numAttrs = 1;
    cudaLaunchKernelEx(&cfg, fused_cluster_kernel, cand_emb, cand_len, score_w, out);
}